// round 1
// baseline (speedup 1.0000x reference)
#include <cuda_runtime.h>
#include <cuda_bf16.h>

#define N_NODES_MAX 50000
#define D 64

// Scratch: per-node transformed features G = features @ W1  (50000 x 64 f32 = 12.8 MB)
__device__ float g_G[N_NODES_MAX * D];
__device__ int g_idx_is64;

// ---------------------------------------------------------------------------
// Detect whether index arrays are int64 or int32.
// Values are node indices in [0, n_nodes). If the buffer is int32 and we read
// it as int64, pairs combine into values >= 2^32 (unless the high word is a
// zero index — vanishingly unlikely for 16 consecutive elements).
// ---------------------------------------------------------------------------
__global__ void detect_idx_kernel(const long long* __restrict__ p, int n, int n_nodes) {
    int is64 = 1;
    int m = n < 16 ? n : 16;
    for (int i = 0; i < m; i++) {
        long long v = p[i];
        if (v < 0 || v >= (long long)n_nodes) { is64 = 0; break; }
    }
    g_idx_is64 = is64;
}

// ---------------------------------------------------------------------------
// Node transform: G[row, :] = features[row, :] @ W1   (W1 is [64, 64], row-major)
// One warp computes 4 rows. Lane owns output columns (lane, lane+32).
// W1 staged in smem; feature values broadcast via shfl.
// ---------------------------------------------------------------------------
__global__ void node_gemm_kernel(const float* __restrict__ feat,
                                 const float* __restrict__ W1,
                                 int n_nodes) {
    __shared__ float Ws[D * D];
    int tid = threadIdx.x;
    for (int i = tid; i < D * D; i += blockDim.x) Ws[i] = W1[i];
    __syncthreads();

    int lane = tid & 31;
    int warpGlobal = (int)((blockIdx.x * blockDim.x + tid) >> 5);
    int totalWarps = (int)((gridDim.x * blockDim.x) >> 5);

    for (int base = warpGlobal * 4; base < n_nodes; base += totalWarps * 4) {
        float fa[4], fb[4];
#pragma unroll
        for (int r = 0; r < 4; r++) {
            int row = base + r;
            if (row < n_nodes) {
                fa[r] = feat[row * D + lane];
                fb[r] = feat[row * D + 32 + lane];
            } else {
                fa[r] = 0.f; fb[r] = 0.f;
            }
        }
        float a0[4] = {0.f, 0.f, 0.f, 0.f};
        float a1[4] = {0.f, 0.f, 0.f, 0.f};
#pragma unroll
        for (int k = 0; k < 32; k++) {
            float w0 = Ws[k * D + lane];
            float w1 = Ws[k * D + 32 + lane];
#pragma unroll
            for (int r = 0; r < 4; r++) {
                float v = __shfl_sync(0xffffffffu, fa[r], k);
                a0[r] = fmaf(v, w0, a0[r]);
                a1[r] = fmaf(v, w1, a1[r]);
            }
        }
#pragma unroll
        for (int k = 0; k < 32; k++) {
            float w0 = Ws[(k + 32) * D + lane];
            float w1 = Ws[(k + 32) * D + 32 + lane];
#pragma unroll
            for (int r = 0; r < 4; r++) {
                float v = __shfl_sync(0xffffffffu, fb[r], k);
                a0[r] = fmaf(v, w0, a0[r]);
                a1[r] = fmaf(v, w1, a1[r]);
            }
        }
#pragma unroll
        for (int r = 0; r < 4; r++) {
            int row = base + r;
            if (row < n_nodes) {
                g_G[row * D + lane] = a0[r];
                g_G[row * D + 32 + lane] = a1[r];
            }
        }
    }
}

// ---------------------------------------------------------------------------
// Edge kernel: 16 lanes per edge, each lane owns 4 contiguous columns (float4).
//   h   = relu(G[src] - G[dst] + b1)
//   att = relu(h . W2 + b2)
//   out = exp(-att) * feat[dst]
// ---------------------------------------------------------------------------
__global__ void edge_kernel(const float* __restrict__ feat,
                            const void* __restrict__ src_idx,
                            const void* __restrict__ dst_idx,
                            const float* __restrict__ b1,
                            const float* __restrict__ W2,
                            const float* __restrict__ b2,
                            float* __restrict__ out,
                            int n_edges) {
    int gid = blockIdx.x * blockDim.x + threadIdx.x;
    int e = gid >> 4;
    int l = threadIdx.x & 15;
    if (e >= n_edges) return;

    int is64 = g_idx_is64;
    long long s, d;
    if (is64) {
        s = ((const long long*)src_idx)[e];
        d = ((const long long*)dst_idx)[e];
    } else {
        s = (long long)((const int*)src_idx)[e];
        d = (long long)((const int*)dst_idx)[e];
    }

    const float4* G4 = (const float4*)g_G;
    float4 gs = __ldg(&G4[s * 16 + l]);
    float4 gd = __ldg(&G4[d * 16 + l]);
    float4 bb = __ldg(&((const float4*)b1)[l]);
    float4 w2 = __ldg(&((const float4*)W2)[l]);

    float h0 = fmaxf(gs.x - gd.x + bb.x, 0.f);
    float h1 = fmaxf(gs.y - gd.y + bb.y, 0.f);
    float h2 = fmaxf(gs.z - gd.z + bb.z, 0.f);
    float h3 = fmaxf(gs.w - gd.w + bb.w, 0.f);

    float p = h0 * w2.x + h1 * w2.y + h2 * w2.z + h3 * w2.w;
    // reduce across the 16-lane group
    p += __shfl_xor_sync(0xffffffffu, p, 1, 16);
    p += __shfl_xor_sync(0xffffffffu, p, 2, 16);
    p += __shfl_xor_sync(0xffffffffu, p, 4, 16);
    p += __shfl_xor_sync(0xffffffffu, p, 8, 16);

    float att = fmaxf(p + __ldg(&b2[0]), 0.f);
    float a = __expf(-att);

    float4 fd = __ldg(&((const float4*)feat)[d * 16 + l]);
    float4 o;
    o.x = a * fd.x; o.y = a * fd.y; o.z = a * fd.z; o.w = a * fd.w;
    ((float4*)out)[(long long)e * 16 + l] = o;
}

// ---------------------------------------------------------------------------
// kernel_launch — inputs (metadata order):
//   0 features [50000,64] f32
//   1 src_idx  [800000]   int64 (or int32, detected)
//   2 dst_idx  [800000]   int64 (or int32, detected)
//   3 W1       [64,64]    f32
//   4 b1       [64]       f32
//   5 W2       [64,1]     f32
//   6 b2       [1]        f32
// output: [800000, 64] f32
// ---------------------------------------------------------------------------
extern "C" void kernel_launch(void* const* d_in, const int* in_sizes, int n_in,
                              void* d_out, int out_size) {
    const float* feat = (const float*)d_in[0];
    const void*  src  = d_in[1];
    const void*  dst  = d_in[2];
    const float* W1   = (const float*)d_in[3];
    const float* b1   = (const float*)d_in[4];
    const float* W2   = (const float*)d_in[5];
    const float* b2   = (const float*)d_in[6];
    float* out = (float*)d_out;

    int n_nodes = in_sizes[0] / D;
    int n_edges = in_sizes[1];
    // if indices arrived as int64, in_sizes may report elements either way;
    // the detection kernel resolves interpretation, n_edges = element count
    // of the src index array per metadata (800000).

    detect_idx_kernel<<<1, 1>>>((const long long*)src, n_edges, n_nodes);

    int gemm_warptasks = (n_nodes + 3) / 4;
    int gemm_blocks = (gemm_warptasks + 7) / 8;  // 8 warps per block
    node_gemm_kernel<<<gemm_blocks, 256>>>(feat, W1, n_nodes);

    long long total_threads = (long long)n_edges * 16;
    int blocks = (int)((total_threads + 255) / 256);
    edge_kernel<<<blocks, 256>>>(feat, src, dst, b1, W2, b2, out, n_edges);
}